// round 2
// baseline (speedup 1.0000x reference)
#include <cuda_runtime.h>
#include <cstdint>

#define BATCH 64
#define SEQ   512
#define DIN   256
#define UNITS 512

// Scratch for the pre-projection xT = x @ T, layout [BATCH, SEQ, UNITS] row-major.
__device__ float g_xT[(size_t)BATCH * SEQ * UNITS];

// ---------------- packed f32x2 helpers (Blackwell FFMA2) ----------------
static __device__ __forceinline__ unsigned long long pack2(float x, float y) {
    unsigned long long r;
    asm("mov.b64 %0, {%1, %2};" : "=l"(r) : "f"(x), "f"(y));
    return r;
}
static __device__ __forceinline__ void fma2(unsigned long long& d,
                                            unsigned long long a,
                                            unsigned long long b) {
    asm("fma.rn.f32x2 %0, %1, %2, %0;" : "+l"(d) : "l"(a), "l"(b));
}
static __device__ __forceinline__ void unpack2(unsigned long long v, float& x, float& y) {
    asm("mov.b64 {%0, %1}, %2;" : "=f"(x), "=f"(y) : "l"(v));
}

// ---------------- Kernel 1: xT = x @ T ----------------
// A: [M=BATCH*SEQ, K=DIN] row-major (x), B: [K=DIN, N=UNITS] row-major (T).
// Tiles: BM=128, BN=128, BK=16; 256 threads; each thread 8x8 outputs as f32x2 pairs.
__global__ __launch_bounds__(256, 2)
void gemm_xT_kernel(const float* __restrict__ A, const float* __restrict__ Bm) {
    __shared__ float As[16 * 132];   // transposed A tile, padded stride 132 (conflict-free)
    __shared__ float Bs[16 * 128];

    const int tid = threadIdx.x;
    const int m0  = blockIdx.y * 128;
    const int n0  = blockIdx.x * 128;
    const int tm0 = (tid >> 4) * 8;   // 16 groups * 8 rows = 128
    const int tn0 = (tid & 15) * 8;   // 16 groups * 8 cols = 128

    unsigned long long acc[8][4];
#pragma unroll
    for (int i = 0; i < 8; i++)
#pragma unroll
        for (int j = 0; j < 4; j++) acc[i][j] = 0ull;

    for (int k0 = 0; k0 < DIN; k0 += 16) {
        // Load A tile (128 rows x 16 cols) as float4, store transposed into As.
#pragma unroll
        for (int s = tid; s < 512; s += 256) {
            int row = s >> 2;
            int c4  = s & 3;
            float4 v = *(const float4*)(A + (size_t)(m0 + row) * DIN + k0 + c4 * 4);
            As[(c4 * 4 + 0) * 132 + row] = v.x;
            As[(c4 * 4 + 1) * 132 + row] = v.y;
            As[(c4 * 4 + 2) * 132 + row] = v.z;
            As[(c4 * 4 + 3) * 132 + row] = v.w;
        }
        // Load B tile (16 rows x 128 cols) directly.
#pragma unroll
        for (int s = tid; s < 512; s += 256) {
            int kk = s >> 5;
            int c4 = s & 31;
            *(float4*)(Bs + kk * 128 + c4 * 4) =
                *(const float4*)(Bm + (size_t)(k0 + kk) * UNITS + n0 + c4 * 4);
        }
        __syncthreads();

#pragma unroll
        for (int kk = 0; kk < 16; kk++) {
            float4 b0 = *(const float4*)(Bs + kk * 128 + tn0);
            float4 b1 = *(const float4*)(Bs + kk * 128 + tn0 + 4);
            unsigned long long bb[4];
            bb[0] = pack2(b0.x, b0.y);
            bb[1] = pack2(b0.z, b0.w);
            bb[2] = pack2(b1.x, b1.y);
            bb[3] = pack2(b1.z, b1.w);

            float4 a0 = *(const float4*)(As + kk * 132 + tm0);
            float4 a1 = *(const float4*)(As + kk * 132 + tm0 + 4);
            float av[8] = {a0.x, a0.y, a0.z, a0.w, a1.x, a1.y, a1.z, a1.w};
#pragma unroll
            for (int i = 0; i < 8; i++) {
                unsigned long long aa = pack2(av[i], av[i]);
#pragma unroll
                for (int j = 0; j < 4; j++) fma2(acc[i][j], aa, bb[j]);
            }
        }
        __syncthreads();
    }

    // Epilogue: write 8x8 tile.
#pragma unroll
    for (int i = 0; i < 8; i++) {
        float o[8];
#pragma unroll
        for (int j = 0; j < 4; j++) unpack2(acc[i][j], o[2 * j], o[2 * j + 1]);
        float* cp = g_xT + (size_t)(m0 + tm0 + i) * UNITS + n0 + tn0;
        *(float4*)(cp)     = make_float4(o[0], o[1], o[2], o[3]);
        *(float4*)(cp + 4) = make_float4(o[4], o[5], o[6], o[7]);
    }
}

// ---------------- Kernel 2: block-diagonal recurrence ----------------
// B = expm(skew tridiagonal with even-position couplings) is EXACTLY 2x2 block
// diagonal over unit pairs (2i, 2i+1). Each (batch, pair) recurrence is
// independent: one thread per (b, pair), 512 sequential steps, 4 FMA/step.
__global__ __launch_bounds__(128)
void rnn_scan_kernel(const float* __restrict__ Bfull,
                     const float* __restrict__ bias,
                     const float* __restrict__ h0,
                     float* __restrict__ out) {
    const int b = blockIdx.y;
    const int p = blockIdx.x * 128 + threadIdx.x;  // pair index 0..255
    const int u = 2 * p;

    // 2x2 block of B for this pair.
    const float B00 = Bfull[(size_t)u * UNITS + u];
    const float B01 = Bfull[(size_t)u * UNITS + u + 1];
    const float B10 = Bfull[(size_t)(u + 1) * UNITS + u];
    const float B11 = Bfull[(size_t)(u + 1) * UNITS + u + 1];
    const float2 bi = *(const float2*)(bias + u);
    float2 h = *(const float2*)(h0 + u);

    const float2* xp = (const float2*)(g_xT + (size_t)b * SEQ * UNITS) + p;  // stride 256 float2 per t
    float2* op = (float2*)out + (size_t)b * (UNITS / 2) + p;                 // stride BATCH*256 per t

    // 4-deep software prefetch ring (indices constant after unroll-by-4).
    float2 buf[4];
#pragma unroll
    for (int j = 0; j < 4; j++) buf[j] = xp[(size_t)j * (UNITS / 2)];

#pragma unroll 4
    for (int t = 0; t < SEQ; t++) {
        float2 xv = buf[t & 3];
        if (t + 4 < SEQ) buf[t & 3] = xp[(size_t)(t + 4) * (UNITS / 2)];

        float z0 = fmaf(h.y, B10, fmaf(h.x, B00, xv.x));
        float z1 = fmaf(h.y, B11, fmaf(h.x, B01, xv.y));

        float m0 = fmaxf(fabsf(z0) + bi.x, 0.0f);
        float m1 = fmaxf(fabsf(z1) + bi.y, 0.0f);
        h.x = (z0 > 0.0f) ? m0 : ((z0 < 0.0f) ? -m0 : 0.0f);
        h.y = (z1 > 0.0f) ? m1 : ((z1 < 0.0f) ? -m1 : 0.0f);

        op[(size_t)t * (BATCH * UNITS / 2)] = h;
    }
}

// ---------------- launch ----------------
extern "C" void kernel_launch(void* const* d_in, const int* in_sizes, int n_in,
                              void* d_out, int out_size) {
    const float* x    = (const float*)d_in[0];  // [64, 512, 256]
    const float* T    = (const float*)d_in[1];  // [256, 512]
    const float* B    = (const float*)d_in[2];  // [512, 512]
    const float* bias = (const float*)d_in[3];  // [512]
    const float* h0   = (const float*)d_in[4];  // [512]
    float* out        = (float*)d_out;          // [512, 64, 512]

    (void)in_sizes; (void)n_in; (void)out_size;

    dim3 g1(UNITS / 128, (BATCH * SEQ) / 128);  // (4, 256)
    gemm_xT_kernel<<<g1, 256>>>(x, T);

    dim3 g2(2, BATCH);                          // 256 pairs / 128 threads, 64 batches
    rnn_scan_kernel<<<g2, 128>>>(B, bias, h0, out);
}

// round 7
// speedup vs baseline: 2.3222x; 2.3222x over previous
#include <cuda_runtime.h>
#include <cuda_bf16.h>
#include <cstdint>

#define BATCH 64
#define SEQ   512
#define DIN   256
#define UNITS 512
#define M_TOT (BATCH * SEQ)   // 32768

// ---------------- scratch (module-static, no allocation APIs) ----------------
__device__ float         g_xT[(size_t)M_TOT * UNITS];   // 64 MB, row-major [M][512]
__device__ __nv_bfloat16 g_Ah[(size_t)M_TOT * DIN];     // 16 MB, [M][K]
__device__ __nv_bfloat16 g_Al[(size_t)M_TOT * DIN];
__device__ __nv_bfloat16 g_Bh[(size_t)UNITS * DIN];     // 256 KB, [N][K] (T transposed)
__device__ __nv_bfloat16 g_Bl[(size_t)UNITS * DIN];

// ---------------- PTX helpers ----------------
static __device__ __forceinline__ uint32_t smem_u32(const void* p) {
    uint32_t a;
    asm("{ .reg .u64 t; cvta.to.shared.u64 t, %1; cvt.u32.u64 %0, t; }" : "=r"(a) : "l"(p));
    return a;
}
static __device__ __forceinline__ void cp16(uint32_t dst, const void* src) {
    asm volatile("cp.async.cg.shared.global [%0], [%1], 16;" :: "r"(dst), "l"(src));
}
static __device__ __forceinline__ void cp_commit() { asm volatile("cp.async.commit_group;"); }
template <int N> static __device__ __forceinline__ void cp_wait() {
    asm volatile("cp.async.wait_group %0;" :: "n"(N));
}

static __device__ __forceinline__ void ldmx4(uint32_t& r0, uint32_t& r1,
                                             uint32_t& r2, uint32_t& r3, uint32_t addr) {
    asm volatile("ldmatrix.sync.aligned.m8n8.x4.shared.b16 {%0,%1,%2,%3}, [%4];"
                 : "=r"(r0), "=r"(r1), "=r"(r2), "=r"(r3) : "r"(addr));
}
static __device__ __forceinline__ void mma16816(float* c, const uint32_t* a,
                                                uint32_t b0, uint32_t b1) {
    asm volatile(
        "mma.sync.aligned.m16n8k16.row.col.f32.bf16.bf16.f32 "
        "{%0,%1,%2,%3}, {%4,%5,%6,%7}, {%8,%9}, {%0,%1,%2,%3};"
        : "+f"(c[0]), "+f"(c[1]), "+f"(c[2]), "+f"(c[3])
        : "r"(a[0]), "r"(a[1]), "r"(a[2]), "r"(a[3]), "r"(b0), "r"(b1));
}

// ---------------- conversion kernels ----------------
__global__ __launch_bounds__(256)
void convert_x_kernel(const float* __restrict__ x) {
    size_t i4 = (size_t)blockIdx.x * 256 + threadIdx.x;   // 4-element groups
    float4 v = ((const float4*)x)[i4];
    float vv[4] = {v.x, v.y, v.z, v.w};
    unsigned short hs[4], ls[4];
#pragma unroll
    for (int j = 0; j < 4; j++) {
        __nv_bfloat16 h = __float2bfloat16_rn(vv[j]);
        __nv_bfloat16 l = __float2bfloat16_rn(vv[j] - __bfloat162float(h));
        hs[j] = *reinterpret_cast<unsigned short*>(&h);
        ls[j] = *reinterpret_cast<unsigned short*>(&l);
    }
    ((uint2*)g_Ah)[i4] = make_uint2((uint32_t)hs[0] | ((uint32_t)hs[1] << 16),
                                    (uint32_t)hs[2] | ((uint32_t)hs[3] << 16));
    ((uint2*)g_Al)[i4] = make_uint2((uint32_t)ls[0] | ((uint32_t)ls[1] << 16),
                                    (uint32_t)ls[2] | ((uint32_t)ls[3] << 16));
}

__global__ __launch_bounds__(256)
void convert_T_kernel(const float* __restrict__ T) {
    int idx = blockIdx.x * 256 + threadIdx.x;   // idx = k*512 + n
    int k = idx >> 9;
    int n = idx & 511;
    float v = T[idx];
    __nv_bfloat16 h = __float2bfloat16_rn(v);
    __nv_bfloat16 l = __float2bfloat16_rn(v - __bfloat162float(h));
    g_Bh[(size_t)n * DIN + k] = h;
    g_Bl[(size_t)n * DIN + k] = l;
}

// ---------------- mma.sync GEMM: g_xT = x @ T via split bf16 (3 terms) ----------------
// Tile 128x128, BK=64, 2-stage cp.async, 8 warps (4m x 2n), warp tile 32x64.
// SMEM stage: Ah@0, Al@16K, Bh@32K, Bl@48K, each [128 rows][64 bf16] SW128-swizzled.
#define GS_STAGE 65536

static __device__ __forceinline__ void gemm_load_chunk(uint32_t sb, int tid,
                                                       int m0, int n0, int kc) {
    const int k0b = kc * 128;   // 64 bf16 = 128 bytes along K
    const char* bases[4] = {
        (const char*)(g_Ah + (size_t)m0 * DIN), (const char*)(g_Al + (size_t)m0 * DIN),
        (const char*)(g_Bh + (size_t)n0 * DIN), (const char*)(g_Bl + (size_t)n0 * DIN)
    };
#pragma unroll
    for (int t = 0; t < 4; t++) {
        const char* g = bases[t];
#pragma unroll
        for (int i = 0; i < 4; i++) {
            int u = tid + i * 256;           // 0..1023
            int row = u >> 3, ku = u & 7;
            uint32_t off = (uint32_t)(row * 128 + ku * 16);
            uint32_t sw = off ^ ((off >> 3) & 0x70);
            cp16(sb + t * 16384 + sw, g + (size_t)row * 512 + k0b + ku * 16);
        }
    }
    cp_commit();
}

// swizzled smem address for (row, byte-col) inside a [128][128B] tile
static __device__ __forceinline__ uint32_t sw_addr(uint32_t base, int row, int colb) {
    return base + (uint32_t)(row * 128) + (uint32_t)(colb ^ ((row & 7) << 4));
}

__global__ __launch_bounds__(256, 1)
void gemm_kernel() {
    extern __shared__ __align__(1024) char sm[];
    const uint32_t sbase = smem_u32(sm);
    const int tid = threadIdx.x;
    const int wid = tid >> 5, lid = tid & 31;
    const int warp_m = wid & 3;        // 4 m-groups of 32 rows
    const int warp_n = wid >> 2;       // 2 n-groups of 64 cols
    const int m0 = blockIdx.y * 128;
    const int n0 = blockIdx.x * 128;

    // per-thread ldmatrix row/col components (x4 quad layout)
    const int lrow = lid & 15;         // row within 16-row group
    const int lqc  = (lid >> 4) * 16;  // +16B for k8-15 quads

    float acc[2][8][4];
#pragma unroll
    for (int i = 0; i < 2; i++)
#pragma unroll
        for (int j = 0; j < 8; j++)
#pragma unroll
            for (int q = 0; q < 4; q++) acc[i][j][q] = 0.0f;

    gemm_load_chunk(sbase, tid, m0, n0, 0);
    gemm_load_chunk(sbase + GS_STAGE, tid, m0, n0, 1);

#pragma unroll
    for (int kc = 0; kc < 4; kc++) {
        if (kc < 3) cp_wait<1>(); else cp_wait<0>();
        __syncthreads();
        const uint32_t sb = sbase + (kc & 1) * GS_STAGE;

#pragma unroll
        for (int pass = 0; pass < 3; pass++) {
            // pass 0: Ah*Bh, pass 1: Ah*Bl, pass 2: Al*Bh
            const uint32_t aS = sb + (pass == 2 ? 16384 : 0);
            const uint32_t bS = sb + 32768 + (pass == 1 ? 16384 : 0);
#pragma unroll
            for (int ks = 0; ks < 4; ks++) {
                const int kb = ks * 32;   // 16 bf16 = 32 bytes
                uint32_t a[2][4];
#pragma unroll
                for (int mt = 0; mt < 2; mt++) {
                    int row = warp_m * 32 + mt * 16 + lrow;
                    ldmx4(a[mt][0], a[mt][1], a[mt][2], a[mt][3],
                          sw_addr(aS, row, kb + lqc));
                }
                uint32_t b[8][2];
#pragma unroll
                for (int ng = 0; ng < 4; ng++) {
                    int row = warp_n * 64 + ng * 16 + lrow;
                    uint32_t r0, r1, r2, r3;
                    ldmx4(r0, r1, r2, r3, sw_addr(bS, row, kb + lqc));
                    b[2 * ng][0] = r0; b[2 * ng + 1][0] = r1;
                    b[2 * ng][1] = r2; b[2 * ng + 1][1] = r3;
                }
#pragma unroll
                for (int mt = 0; mt < 2; mt++)
#pragma unroll
                    for (int nt = 0; nt < 8; nt++)
                        mma16816(acc[mt][nt], a[mt], b[nt][0], b[nt][1]);
            }
        }
        __syncthreads();
        if (kc < 2) gemm_load_chunk(sb, tid, m0, n0, kc + 2);
    }

    // Epilogue: write c-fragments directly (float2 per quad-half).
    const int gID = lid >> 2, tg = lid & 3;
#pragma unroll
    for (int mt = 0; mt < 2; mt++) {
#pragma unroll
        for (int nt = 0; nt < 8; nt++) {
            int m_lo = m0 + warp_m * 32 + mt * 16 + gID;
            int n    = n0 + warp_n * 64 + nt * 8 + tg * 2;
            *(float2*)(g_xT + (size_t)m_lo * UNITS + n) =
                make_float2(acc[mt][nt][0], acc[mt][nt][1]);
            *(float2*)(g_xT + (size_t)(m_lo + 8) * UNITS + n) =
                make_float2(acc[mt][nt][2], acc[mt][nt][3]);
        }
    }
}

// ---------------- scan kernel: smem-staged block-diagonal recurrence ----------------
// B = expm(skew, even-position couplings) is EXACTLY 2x2 block diagonal. One
// thread per (batch, pair); 32-step chunks staged via 2-deep cp.async.
__global__ __launch_bounds__(128, 1)
void scan_kernel(const float* __restrict__ Bfull, const float* __restrict__ bias,
                 const float* __restrict__ h0, float* __restrict__ out) {
    extern __shared__ __align__(1024) char sm[];   // 2 x 32KB
    const uint32_t sbase = smem_u32(sm);
    const int tid = threadIdx.x;
    const int b = blockIdx.y;
    const int u0 = blockIdx.x * 256;
    const int u = u0 + 2 * tid;

    const float B00 = Bfull[(size_t)u * UNITS + u];
    const float B01 = Bfull[(size_t)u * UNITS + u + 1];
    const float B10 = Bfull[(size_t)(u + 1) * UNITS + u];
    const float B11 = Bfull[(size_t)(u + 1) * UNITS + u + 1];
    const float2 bi = *(const float2*)(bias + u);
    float2 h = *(const float2*)(h0 + u);

    const float* xbase = g_xT + (size_t)b * SEQ * UNITS + u0;

#define SCAN_LOAD(tc) do {                                                       \
        uint32_t dst = sbase + ((tc) & 1) * 32768;                               \
        const float* src = xbase + (size_t)(tc) * 32 * UNITS;                    \
        _Pragma("unroll")                                                        \
        for (int i = 0; i < 16; i++) {                                           \
            int uq = tid + i * 128;                                              \
            int row = uq >> 6, cu = uq & 63;                                     \
            cp16(dst + row * 1024 + cu * 16, src + (size_t)row * UNITS + cu * 4);\
        }                                                                        \
        cp_commit();                                                             \
    } while (0)

    SCAN_LOAD(0);
    SCAN_LOAD(1);

    float2* op = (float2*)(out + (size_t)b * UNITS + u0) + tid;   // +t*16384 float2/step

    for (int tc = 0; tc < 16; tc++) {
        if (tc < 15) cp_wait<1>(); else cp_wait<0>();
        __syncthreads();
        const float2* xs = (const float2*)(sm + (tc & 1) * 32768) + tid;
#pragma unroll
        for (int lt = 0; lt < 32; lt++) {
            float2 xv = xs[lt * 128];
            float z0 = fmaf(h.y, B10, fmaf(h.x, B00, xv.x));
            float z1 = fmaf(h.y, B11, fmaf(h.x, B01, xv.y));
            float m0 = fmaxf(fabsf(z0) + bi.x, 0.0f);
            float m1 = fmaxf(fabsf(z1) + bi.y, 0.0f);
            h.x = (z0 > 0.0f) ? m0 : ((z0 < 0.0f) ? -m0 : 0.0f);
            h.y = (z1 > 0.0f) ? m1 : ((z1 < 0.0f) ? -m1 : 0.0f);
            op[(size_t)(tc * 32 + lt) * (BATCH * UNITS / 2)] = h;
        }
        __syncthreads();
        if (tc < 14) SCAN_LOAD(tc + 2);
    }
#undef SCAN_LOAD
}

// ---------------- launch ----------------
extern "C" void kernel_launch(void* const* d_in, const int* in_sizes, int n_in,
                              void* d_out, int out_size) {
    const float* x    = (const float*)d_in[0];
    const float* T    = (const float*)d_in[1];
    const float* B    = (const float*)d_in[2];
    const float* bias = (const float*)d_in[3];
    const float* h0   = (const float*)d_in[4];
    float* out        = (float*)d_out;
    (void)in_sizes; (void)n_in; (void)out_size;

    cudaFuncSetAttribute(gemm_kernel, cudaFuncAttributeMaxDynamicSharedMemorySize,
                         2 * GS_STAGE);
    cudaFuncSetAttribute(scan_kernel, cudaFuncAttributeMaxDynamicSharedMemorySize, 65536);

    convert_x_kernel<<<(M_TOT * DIN / 4) / 256, 256>>>(x);       // 8192 CTAs
    convert_T_kernel<<<(DIN * UNITS) / 256, 256>>>(T);           // 512 CTAs

    dim3 gg(UNITS / 128, M_TOT / 128);                           // (4, 256)
    gemm_kernel<<<gg, 256, 2 * GS_STAGE>>>();

    dim3 gs(UNITS / 256, BATCH);                                 // (2, 64)
    scan_kernel<<<gs, 128, 65536>>>(B, bias, h0, out);
}